// round 8
// baseline (speedup 1.0000x reference)
#include <cuda_runtime.h>
#include <cstdint>

// Problem constants
#define B_      16
#define C_      64
#define HW_     65536      // 256*256

// Radix sort: 4 stable LSD passes of 8 bits over the 32-bit ordered-float
// value (high half of a u64 key). Low bits: channel<<16 | spatial(16).
// Keys generated in spatial order; stability => jnp argsort tie order.
#define THREADS 256
#define NW      8
#define IPT     4
#define BSIZE   1024               // THREADS * IPT
#define NBLK    64                 // HW_ / BSIZE
#define GRID    (B_ * NBLK)        // 1024 scatter blocks
#define HISTSZ  (B_ * 256 * NBLK)  // 262144 entries

__device__ __align__(16) unsigned long long g_kv0[B_ * HW_];
__device__ __align__(16) unsigned long long g_kv1[B_ * HW_];
__device__ __align__(16) unsigned int       g_histA[HISTSZ];
__device__ __align__(16) unsigned int       g_histB[HISTSZ];

__device__ __forceinline__ unsigned int f2ord(float f) {
    unsigned int u = __float_as_uint(f);
    return (u & 0x80000000u) ? ~u : (u | 0x80000000u);
}

// Diagnostic no-op: shifts compute_keys into the ncu capture slot (#4).
__global__ void noop_kernel() {}

// -------------------------------------------------------------------------
// Kernel 1: channel max + argmax (first occurrence), emit u64 keys with
// channel+spatial embedded. grid = 1024 x 256, 4 consecutive positions per
// thread via float4 streaming loads.
// -------------------------------------------------------------------------
__global__ void compute_keys_kernel(const float* __restrict__ x) {
    int gid   = blockIdx.x * 256 + threadIdx.x;
    int batch = gid >> 14;
    int q     = gid & 16383;

    const float4* xb = reinterpret_cast<const float4*>(x)
                       + (size_t)batch * (C_ * (HW_ / 4)) + q;

    float4 best = xb[0];
    int c0 = 0, c1 = 0, c2 = 0, c3 = 0;
    #pragma unroll
    for (int c = 1; c < C_; ++c) {
        float4 v = xb[(size_t)c * (HW_ / 4)];
        if (v.x > best.x) { best.x = v.x; c0 = c; }
        if (v.y > best.y) { best.y = v.y; c1 = c; }
        if (v.z > best.z) { best.z = v.z; c2 = c; }
        if (v.w > best.w) { best.w = v.w; c3 = c; }
    }

    size_t o = (size_t)batch * HW_;
    unsigned int s = (unsigned int)q * 4u;
    ulonglong2 k01, k23;
    k01.x = ((unsigned long long)f2ord(best.x) << 32) | ((unsigned)c0 << 16) | (s + 0u);
    k01.y = ((unsigned long long)f2ord(best.y) << 32) | ((unsigned)c1 << 16) | (s + 1u);
    k23.x = ((unsigned long long)f2ord(best.z) << 32) | ((unsigned)c2 << 16) | (s + 2u);
    k23.y = ((unsigned long long)f2ord(best.w) << 32) | ((unsigned)c3 << 16) | (s + 3u);
    *reinterpret_cast<ulonglong2*>(g_kv0 + o + s)     = k01;
    *reinterpret_cast<ulonglong2*>(g_kv0 + o + s + 2) = k23;
}

// -------------------------------------------------------------------------
// Kernel 2: pass-1 per-scatter-block histogram (digit = bits [32,40)).
// Also zeroes g_histB. grid = 1024 x 256; 4 kv per thread via ulonglong2.
// -------------------------------------------------------------------------
__global__ void hist1_kernel() {
    __shared__ unsigned int h[256];
    int tid = threadIdx.x;
    h[tid] = 0;
    __syncthreads();

    size_t base = (size_t)blockIdx.x * BSIZE;
    ulonglong2 v0 = *reinterpret_cast<const ulonglong2*>(g_kv0 + base + tid * 2);
    ulonglong2 v1 = *reinterpret_cast<const ulonglong2*>(g_kv0 + base + 512 + tid * 2);
    atomicAdd(&h[(unsigned)(v0.x >> 32) & 255u], 1u);
    atomicAdd(&h[(unsigned)(v0.y >> 32) & 255u], 1u);
    atomicAdd(&h[(unsigned)(v1.x >> 32) & 255u], 1u);
    atomicAdd(&h[(unsigned)(v1.y >> 32) & 255u], 1u);
    __syncthreads();

    int batch = blockIdx.x >> 6, local = blockIdx.x & 63;
    size_t hidx = ((size_t)batch * 256 + tid) * NBLK + local;
    g_histA[hidx] = h[tid];
    g_histB[hidx] = 0u;
}

// -------------------------------------------------------------------------
// Kernel 3: per-batch exclusive scan of 16384 hist entries (bin-major,
// block-minor). grid = 16 x 1024. Optionally zeroes the other hist buffer.
// -------------------------------------------------------------------------
__global__ void scan_kernel(int which, int zero_other) {
    __shared__ unsigned int warp_sums[32];
    unsigned int* hist = (which ? g_histB : g_histA) + (size_t)blockIdx.x * 16384;
    int tid = threadIdx.x;
    int lane = tid & 31, w = tid >> 5;

    unsigned int v[16];
    unsigned int sum = 0;
    #pragma unroll
    for (int j = 0; j < 16; ++j) { v[j] = hist[tid * 16 + j]; sum += v[j]; }

    unsigned int inc = sum;
    #pragma unroll
    for (int o = 1; o < 32; o <<= 1) {
        unsigned int t = __shfl_up_sync(0xffffffffu, inc, o);
        if (lane >= o) inc += t;
    }
    if (lane == 31) warp_sums[w] = inc;
    __syncthreads();
    if (w == 0) {
        unsigned int ws = warp_sums[lane];
        #pragma unroll
        for (int o = 1; o < 32; o <<= 1) {
            unsigned int t = __shfl_up_sync(0xffffffffu, ws, o);
            if (lane >= o) ws += t;
        }
        warp_sums[lane] = ws;
    }
    __syncthreads();

    unsigned int excl = inc - sum + (w > 0 ? warp_sums[w - 1] : 0u);
    #pragma unroll
    for (int j = 0; j < 16; ++j) { hist[tid * 16 + j] = excl; excl += v[j]; }

    if (zero_other) {
        unsigned int* o = (which ? g_histA : g_histB) + (size_t)blockIdx.x * 16384;
        #pragma unroll
        for (int j = 0; j < 16; ++j) o[tid * 16 + j] = 0u;
    }
}

// -------------------------------------------------------------------------
// Kernel 4: stable scatter. Streaming-ballot parallel ranking (only one
// item's ballots live at a time -> low registers), smem exchange for
// coalesced writes. WHICH=0: kv0->kv1, histA cur, histB next. grid=1024x256.
// -------------------------------------------------------------------------
template <int SHIFT, int WHICH, bool LAST>
__global__ void __launch_bounds__(THREADS, 5)
scatter_kernel(float4* __restrict__ outv) {
    __shared__ unsigned int       wh[NW][256];
    __shared__ unsigned long long s_kv[BSIZE];
    __shared__ unsigned int       dstart[256];
    __shared__ unsigned int       gbase[256];
    __shared__ unsigned int       sw[NW];

    const unsigned long long* __restrict__ in_kv    = WHICH ? g_kv1 : g_kv0;
    unsigned long long*       __restrict__ out_kv   = WHICH ? g_kv0 : g_kv1;
    const unsigned int*       __restrict__ cur_hist = WHICH ? g_histB : g_histA;
    unsigned int*             __restrict__ next_hist= WHICH ? g_histA : g_histB;

    int tid = threadIdx.x;
    int w = tid >> 5, lane = tid & 31;
    unsigned int lt = (1u << lane) - 1u;
    for (int j = tid; j < NW * 256; j += THREADS)
        (&wh[0][0])[j] = 0;
    __syncthreads();

    int blk = blockIdx.x, batch = blk >> 6, local = blk & 63;
    size_t base = (size_t)blk * BSIZE + (size_t)w * (32 * IPT);

    unsigned long long kv[IPT];
    unsigned int d[IPT];
    unsigned int rank[IPT];

    #pragma unroll
    for (int i = 0; i < IPT; ++i) {
        kv[i] = in_kv[base + i * 32 + lane];
        d[i] = (unsigned)(kv[i] >> (32 + SHIFT)) & 255u;
        rank[i] = 0;
    }

    // Streaming ranking: for each item j, publish its 8 digit-bit ballots,
    // update ranks of all items i >= j, then discard the ballots.
    // rank[i] = #equal-digit items earlier in warp order (item-major).
    #pragma unroll
    for (int j = 0; j < IPT; ++j) {
        unsigned int bal[8];
        #pragma unroll
        for (int b = 0; b < 8; ++b)
            bal[b] = __ballot_sync(0xffffffffu, (d[j] >> b) & 1u);
        #pragma unroll
        for (int i = j; i < IPT; ++i) {
            unsigned int m = 0xffffffffu;
            #pragma unroll
            for (int b = 0; b < 8; ++b)
                m &= bal[b] ^ (((d[i] >> b) & 1u) - 1u);
            if (i == j) {
                unsigned int rw = __popc(m & lt);
                rank[i] += rw;
                if (rw == 0)                       // item-digit leader publishes
                    atomicAdd(&wh[w][d[i]], __popc(m));
            } else {
                rank[i] += __popc(m);
            }
        }
    }
    __syncthreads();

    // Per-bin cross-warp exclusive scan (bin = tid); running = bin total.
    unsigned int running = 0;
    #pragma unroll
    for (int q = 0; q < NW; ++q) {
        unsigned int t = wh[q][tid];
        wh[q][tid] = running;
        running += t;
    }

    // Block-wide exclusive scan over the 256 bin totals.
    unsigned int inc = running;
    #pragma unroll
    for (int o = 1; o < 32; o <<= 1) {
        unsigned int t = __shfl_up_sync(0xffffffffu, inc, o);
        if (lane >= o) inc += t;
    }
    if (lane == 31) sw[w] = inc;
    __syncthreads();
    if (tid == 0) {
        unsigned int r = 0;
        #pragma unroll
        for (int q = 0; q < NW; ++q) { unsigned int t = sw[q]; sw[q] = r; r += t; }
    }
    __syncthreads();
    unsigned int excl = inc - running + sw[w];
    dstart[tid] = excl;
    gbase[tid]  = cur_hist[((size_t)batch * 256 + tid) * NBLK + local] - excl;
    __syncthreads();

    // Exchange into block-digit-sorted order.
    #pragma unroll
    for (int i = 0; i < IPT; ++i) {
        unsigned int p = dstart[d[i]] + wh[w][d[i]] + rank[i];
        s_kv[p] = kv[i];
    }
    __syncthreads();

    // Coalesced write-out; global pos = gbase[digit] + p.
    size_t obase = (size_t)batch * HW_;
    #pragma unroll
    for (int j = 0; j < IPT; ++j) {
        unsigned int p = (unsigned int)tid + j * THREADS;
        unsigned long long k = s_kv[p];
        unsigned int dd = (unsigned)(k >> (32 + SHIFT)) & 255u;
        unsigned int pos = gbase[dd] + p;
        if (!LAST) {
            out_kv[obase + pos] = k;
            unsigned int d2 = (unsigned)(k >> (40 + SHIFT)) & 255u;
            atomicAdd(&next_hist[((size_t)batch * 256 + d2) * NBLK + (pos >> 10)], 1u);
        } else {
            unsigned int hi = (unsigned int)(k >> 32);
            unsigned int u  = (hi & 0x80000000u) ? (hi ^ 0x80000000u) : ~hi;
            unsigned int lo = (unsigned int)k & 0x3FFFFFu;   // c<<16 | s  == flat idx
            unsigned int s  = lo & 0xFFFFu;
            float4 o;
            o.x = __uint_as_float(u);
            o.y = (float)lo;                      // c*65536 + s, < 2^22, exact
            o.z = (float)(s >> 8);                // row (W=256)
            o.w = (float)(s & 255u);              // col
            outv[obase + pos] = o;
        }
    }
}

// -------------------------------------------------------------------------
extern "C" void kernel_launch(void* const* d_in, const int* in_sizes, int n_in,
                              void* d_out, int out_size) {
    const float* x = (const float*)d_in[0];
    float4* out = (float4*)d_out;

    // Three no-ops so compute_keys lands in the ncu capture slot (#4).
    noop_kernel<<<1, 32>>>();
    noop_kernel<<<1, 32>>>();
    noop_kernel<<<1, 32>>>();

    compute_keys_kernel<<<1024, 256>>>(x);
    hist1_kernel<<<GRID, THREADS>>>();                     // hist1 -> A, zero B

    scan_kernel<<<16, 1024>>>(0, 0);                       // scan A
    scatter_kernel<0, 0, false><<<GRID, THREADS>>>(nullptr);   // kv0->kv1, hist2->B

    scan_kernel<<<16, 1024>>>(1, 1);                       // scan B, zero A
    scatter_kernel<8, 1, false><<<GRID, THREADS>>>(nullptr);   // kv1->kv0, hist3->A

    scan_kernel<<<16, 1024>>>(0, 1);                       // scan A, zero B
    scatter_kernel<16, 0, false><<<GRID, THREADS>>>(nullptr);  // kv0->kv1, hist4->B

    scan_kernel<<<16, 1024>>>(1, 0);                       // scan B
    scatter_kernel<24, 1, true><<<GRID, THREADS>>>(out);       // kv1->d_out
}

// round 9
// speedup vs baseline: 1.1322x; 1.1322x over previous
#include <cuda_runtime.h>
#include <cstdint>

// Problem constants
#define B_      16
#define C_      64
#define HW_     65536      // 256*256

// Radix sort: 4 stable LSD passes of 8 bits over the 32-bit ordered-float
// value (high half of a u64 key). Low bits: channel<<16 | spatial(16).
// Keys generated in spatial order; stability => jnp argsort tie order.
#define THREADS 256
#define NW      8
#define IPT     4
#define BSIZE   1024               // THREADS * IPT
#define NBLK    64                 // HW_ / BSIZE
#define GRID    (B_ * NBLK)        // 1024 scatter blocks
#define HISTSZ  (B_ * 256 * NBLK)  // 262144 entries

__device__ __align__(16) unsigned long long g_kv0[B_ * HW_];
__device__ __align__(16) unsigned long long g_kv1[B_ * HW_];
__device__ __align__(16) unsigned int       g_histA[HISTSZ];
__device__ __align__(16) unsigned int       g_histB[HISTSZ];

__device__ __forceinline__ unsigned int f2ord(float f) {
    unsigned int u = __float_as_uint(f);
    return (u & 0x80000000u) ? ~u : (u | 0x80000000u);
}

// -------------------------------------------------------------------------
// Kernel 1: channel max + argmax (first occurrence), emit u64 keys.
// Channel axis split 4-ways across lanes: each thread reduces 16 channels
// for 4 pixels; shfl_xor(1),(2) combine the 4 chunk-lanes. 4x threads of
// the old version -> latency hiding without a 95-reg load window.
// grid = 4096 x 256.
// -------------------------------------------------------------------------
__global__ void compute_keys_kernel(const float* __restrict__ x) {
    int gid   = blockIdx.x * 256 + threadIdx.x;   // 0 .. 1048575
    int chunk = gid & 3;                          // channel chunk (16 ch each)
    int qg    = gid >> 2;                         // global pixel-group
    int batch = qg >> 14;
    int q     = qg & 16383;

    const float4* xb = reinterpret_cast<const float4*>(x)
                       + (size_t)batch * (C_ * (HW_ / 4))
                       + (size_t)(chunk * 16) * (HW_ / 4) + q;

    float4 best = xb[0];
    int c0 = 0, c1 = 0, c2 = 0, c3 = 0;
    #pragma unroll
    for (int c = 1; c < 16; ++c) {
        float4 v = xb[(size_t)c * (HW_ / 4)];
        if (v.x > best.x) { best.x = v.x; c0 = c; }
        if (v.y > best.y) { best.y = v.y; c1 = c; }
        if (v.z > best.z) { best.z = v.z; c2 = c; }
        if (v.w > best.w) { best.w = v.w; c3 = c; }
    }
    int cb = chunk * 16;
    c0 += cb; c1 += cb; c2 += cb; c3 += cb;

    // Cross-chunk combine. Lower chunk = lower channels, so the tie rule
    // (equal value -> smaller channel) reproduces argmax first-occurrence.
    #pragma unroll
    for (int m = 1; m <= 2; m <<= 1) {
        float ox = __shfl_xor_sync(0xffffffffu, best.x, m);
        float oy = __shfl_xor_sync(0xffffffffu, best.y, m);
        float oz = __shfl_xor_sync(0xffffffffu, best.z, m);
        float ow = __shfl_xor_sync(0xffffffffu, best.w, m);
        int   o0 = __shfl_xor_sync(0xffffffffu, c0, m);
        int   o1 = __shfl_xor_sync(0xffffffffu, c1, m);
        int   o2 = __shfl_xor_sync(0xffffffffu, c2, m);
        int   o3 = __shfl_xor_sync(0xffffffffu, c3, m);
        if (ox > best.x || (ox == best.x && o0 < c0)) { best.x = ox; c0 = o0; }
        if (oy > best.y || (oy == best.y && o1 < c1)) { best.y = oy; c1 = o1; }
        if (oz > best.z || (oz == best.z && o2 < c2)) { best.z = oz; c2 = o2; }
        if (ow > best.w || (ow == best.w && o3 < c3)) { best.w = ow; c3 = o3; }
    }

    if (chunk == 0) {
        size_t o = (size_t)batch * HW_;
        unsigned int s = (unsigned int)q * 4u;
        ulonglong2 k01, k23;
        k01.x = ((unsigned long long)f2ord(best.x) << 32) | ((unsigned)c0 << 16) | (s + 0u);
        k01.y = ((unsigned long long)f2ord(best.y) << 32) | ((unsigned)c1 << 16) | (s + 1u);
        k23.x = ((unsigned long long)f2ord(best.z) << 32) | ((unsigned)c2 << 16) | (s + 2u);
        k23.y = ((unsigned long long)f2ord(best.w) << 32) | ((unsigned)c3 << 16) | (s + 3u);
        *reinterpret_cast<ulonglong2*>(g_kv0 + o + s)     = k01;
        *reinterpret_cast<ulonglong2*>(g_kv0 + o + s + 2) = k23;
    }
}

// -------------------------------------------------------------------------
// Kernel 2: pass-1 per-scatter-block histogram (digit = bits [32,40)).
// Also zeroes g_histB. grid = 1024 x 256; 4 kv per thread via ulonglong2.
// -------------------------------------------------------------------------
__global__ void hist1_kernel() {
    __shared__ unsigned int h[256];
    int tid = threadIdx.x;
    h[tid] = 0;
    __syncthreads();

    size_t base = (size_t)blockIdx.x * BSIZE;
    ulonglong2 v0 = *reinterpret_cast<const ulonglong2*>(g_kv0 + base + tid * 2);
    ulonglong2 v1 = *reinterpret_cast<const ulonglong2*>(g_kv0 + base + 512 + tid * 2);
    atomicAdd(&h[(unsigned)(v0.x >> 32) & 255u], 1u);
    atomicAdd(&h[(unsigned)(v0.y >> 32) & 255u], 1u);
    atomicAdd(&h[(unsigned)(v1.x >> 32) & 255u], 1u);
    atomicAdd(&h[(unsigned)(v1.y >> 32) & 255u], 1u);
    __syncthreads();

    int batch = blockIdx.x >> 6, local = blockIdx.x & 63;
    size_t hidx = ((size_t)batch * 256 + tid) * NBLK + local;
    g_histA[hidx] = h[tid];
    g_histB[hidx] = 0u;
}

// -------------------------------------------------------------------------
// Kernel 3: per-batch exclusive scan of 16384 hist entries (bin-major,
// block-minor). grid = 16 x 1024. Optionally zeroes the other hist buffer.
// -------------------------------------------------------------------------
__global__ void scan_kernel(int which, int zero_other) {
    __shared__ unsigned int warp_sums[32];
    unsigned int* hist = (which ? g_histB : g_histA) + (size_t)blockIdx.x * 16384;
    int tid = threadIdx.x;
    int lane = tid & 31, w = tid >> 5;

    unsigned int v[16];
    unsigned int sum = 0;
    #pragma unroll
    for (int j = 0; j < 16; ++j) { v[j] = hist[tid * 16 + j]; sum += v[j]; }

    unsigned int inc = sum;
    #pragma unroll
    for (int o = 1; o < 32; o <<= 1) {
        unsigned int t = __shfl_up_sync(0xffffffffu, inc, o);
        if (lane >= o) inc += t;
    }
    if (lane == 31) warp_sums[w] = inc;
    __syncthreads();
    if (w == 0) {
        unsigned int ws = warp_sums[lane];
        #pragma unroll
        for (int o = 1; o < 32; o <<= 1) {
            unsigned int t = __shfl_up_sync(0xffffffffu, ws, o);
            if (lane >= o) ws += t;
        }
        warp_sums[lane] = ws;
    }
    __syncthreads();

    unsigned int excl = inc - sum + (w > 0 ? warp_sums[w - 1] : 0u);
    #pragma unroll
    for (int j = 0; j < 16; ++j) { hist[tid * 16 + j] = excl; excl += v[j]; }

    if (zero_other) {
        unsigned int* o = (which ? g_histA : g_histB) + (size_t)blockIdx.x * 16384;
        #pragma unroll
        for (int j = 0; j < 16; ++j) o[tid * 16 + j] = 0u;
    }
}

// -------------------------------------------------------------------------
// Kernel 4: stable scatter. Streaming-ballot parallel ranking, smem
// exchange for coalesced writes. WHICH=0: kv0->kv1, histA cur, histB next.
// grid = 1024 x 256.
// -------------------------------------------------------------------------
template <int SHIFT, int WHICH, bool LAST>
__global__ void __launch_bounds__(THREADS, 5)
scatter_kernel(float4* __restrict__ outv) {
    __shared__ unsigned int       wh[NW][256];
    __shared__ unsigned long long s_kv[BSIZE];
    __shared__ unsigned int       dstart[256];
    __shared__ unsigned int       gbase[256];
    __shared__ unsigned int       sw[NW];

    const unsigned long long* __restrict__ in_kv    = WHICH ? g_kv1 : g_kv0;
    unsigned long long*       __restrict__ out_kv   = WHICH ? g_kv0 : g_kv1;
    const unsigned int*       __restrict__ cur_hist = WHICH ? g_histB : g_histA;
    unsigned int*             __restrict__ next_hist= WHICH ? g_histA : g_histB;

    int tid = threadIdx.x;
    int w = tid >> 5, lane = tid & 31;
    unsigned int lt = (1u << lane) - 1u;
    for (int j = tid; j < NW * 256; j += THREADS)
        (&wh[0][0])[j] = 0;
    __syncthreads();

    int blk = blockIdx.x, batch = blk >> 6, local = blk & 63;
    size_t base = (size_t)blk * BSIZE + (size_t)w * (32 * IPT);

    unsigned long long kv[IPT];
    unsigned int d[IPT];
    unsigned int rank[IPT];

    #pragma unroll
    for (int i = 0; i < IPT; ++i) {
        kv[i] = in_kv[base + i * 32 + lane];
        d[i] = (unsigned)(kv[i] >> (32 + SHIFT)) & 255u;
        rank[i] = 0;
    }

    // Streaming ranking: for each item j, publish its 8 digit-bit ballots,
    // update ranks of all items i >= j, then discard the ballots.
    #pragma unroll
    for (int j = 0; j < IPT; ++j) {
        unsigned int bal[8];
        #pragma unroll
        for (int b = 0; b < 8; ++b)
            bal[b] = __ballot_sync(0xffffffffu, (d[j] >> b) & 1u);
        #pragma unroll
        for (int i = j; i < IPT; ++i) {
            unsigned int m = 0xffffffffu;
            #pragma unroll
            for (int b = 0; b < 8; ++b)
                m &= bal[b] ^ (((d[i] >> b) & 1u) - 1u);
            if (i == j) {
                unsigned int rw = __popc(m & lt);
                rank[i] += rw;
                if (rw == 0)                       // item-digit leader publishes
                    atomicAdd(&wh[w][d[i]], __popc(m));
            } else {
                rank[i] += __popc(m);
            }
        }
    }
    __syncthreads();

    // Per-bin cross-warp exclusive scan (bin = tid); running = bin total.
    unsigned int running = 0;
    #pragma unroll
    for (int q = 0; q < NW; ++q) {
        unsigned int t = wh[q][tid];
        wh[q][tid] = running;
        running += t;
    }

    // Block-wide exclusive scan over the 256 bin totals.
    unsigned int inc = running;
    #pragma unroll
    for (int o = 1; o < 32; o <<= 1) {
        unsigned int t = __shfl_up_sync(0xffffffffu, inc, o);
        if (lane >= o) inc += t;
    }
    if (lane == 31) sw[w] = inc;
    __syncthreads();
    if (tid == 0) {
        unsigned int r = 0;
        #pragma unroll
        for (int q = 0; q < NW; ++q) { unsigned int t = sw[q]; sw[q] = r; r += t; }
    }
    __syncthreads();
    unsigned int excl = inc - running + sw[w];
    dstart[tid] = excl;
    gbase[tid]  = cur_hist[((size_t)batch * 256 + tid) * NBLK + local] - excl;
    __syncthreads();

    // Exchange into block-digit-sorted order.
    #pragma unroll
    for (int i = 0; i < IPT; ++i) {
        unsigned int p = dstart[d[i]] + wh[w][d[i]] + rank[i];
        s_kv[p] = kv[i];
    }
    __syncthreads();

    // Coalesced write-out; global pos = gbase[digit] + p.
    size_t obase = (size_t)batch * HW_;
    #pragma unroll
    for (int j = 0; j < IPT; ++j) {
        unsigned int p = (unsigned int)tid + j * THREADS;
        unsigned long long k = s_kv[p];
        unsigned int dd = (unsigned)(k >> (32 + SHIFT)) & 255u;
        unsigned int pos = gbase[dd] + p;
        if (!LAST) {
            out_kv[obase + pos] = k;
            unsigned int d2 = (unsigned)(k >> (40 + SHIFT)) & 255u;
            atomicAdd(&next_hist[((size_t)batch * 256 + d2) * NBLK + (pos >> 10)], 1u);
        } else {
            unsigned int hi = (unsigned int)(k >> 32);
            unsigned int u  = (hi & 0x80000000u) ? (hi ^ 0x80000000u) : ~hi;
            unsigned int lo = (unsigned int)k & 0x3FFFFFu;   // c<<16 | s  == flat idx
            unsigned int s  = lo & 0xFFFFu;
            float4 o;
            o.x = __uint_as_float(u);
            o.y = (float)lo;                      // c*65536 + s, < 2^22, exact
            o.z = (float)(s >> 8);                // row (W=256)
            o.w = (float)(s & 255u);              // col
            outv[obase + pos] = o;
        }
    }
}

// -------------------------------------------------------------------------
extern "C" void kernel_launch(void* const* d_in, const int* in_sizes, int n_in,
                              void* d_out, int out_size) {
    const float* x = (const float*)d_in[0];
    float4* out = (float4*)d_out;

    compute_keys_kernel<<<4096, 256>>>(x);
    hist1_kernel<<<GRID, THREADS>>>();                     // hist1 -> A, zero B

    scan_kernel<<<16, 1024>>>(0, 0);                       // scan A
    scatter_kernel<0, 0, false><<<GRID, THREADS>>>(nullptr);   // kv0->kv1, hist2->B

    scan_kernel<<<16, 1024>>>(1, 1);                       // scan B, zero A
    scatter_kernel<8, 1, false><<<GRID, THREADS>>>(nullptr);   // kv1->kv0, hist3->A

    scan_kernel<<<16, 1024>>>(0, 1);                       // scan A, zero B
    scatter_kernel<16, 0, false><<<GRID, THREADS>>>(nullptr);  // kv0->kv1, hist4->B

    scan_kernel<<<16, 1024>>>(1, 0);                       // scan B
    scatter_kernel<24, 1, true><<<GRID, THREADS>>>(out);       // kv1->d_out
}